// round 10
// baseline (speedup 1.0000x reference)
#include <cuda_runtime.h>
#include <cstdint>
#include <math.h>

// ---------------- problem constants ----------------
#define BATCH   4
#define C_IN    2048
#define CH      512
#define HWDIM   50
#define A_NUM   9
#define N_ANCH  (HWDIM*HWDIM*A_NUM)   // 22500
#define K_PRE   2000
#define TOPN    1000
#define NPIX    (BATCH*HWDIM*HWDIM)   // 10000
#define KDIM    (C_IN*9)              // 18432

// Eigen gebp kc on aarch64 (default l1=16KB, NEON mr=12/nr=4): kc = 248
#define CHUNK_K 248

// ---------------- device scratch (no allocs allowed) ----------------
__device__ float g_wT[KDIM*CH];                    // [c*9+tap][oc]  37.7MB
__device__ float g_h[NPIX*CH];                     // NHWC conv out  20.5MB
__device__ float g_scores[BATCH*N_ANCH];
__device__ float g_boxes[BATCH*N_ANCH*4];
__device__ float g_btop[BATCH*K_PRE*4];
__device__ unsigned long long g_mask[BATCH*K_PRE*32];

// correctly-rounded float exp: fp64 exp, single rounding to fp32
__device__ __forceinline__ float exp_cr(float x) {
    return (float)exp((double)x);
}

// ---------------- weight transpose: [oc][c*9] -> [c*9][oc] ----------------
__global__ __launch_bounds__(1024) void transpose_w_kernel(const float* __restrict__ w) {
    __shared__ float tile[32][33];
    int kx = blockIdx.x*32 + threadIdx.x;   // k dim (18432 = 576*32 exact)
    int oy = blockIdx.y*32 + threadIdx.y;   // oc dim (512 = 16*32 exact)
    tile[threadIdx.y][threadIdx.x] = w[oy*KDIM + kx];
    __syncthreads();
    int oc = blockIdx.y*32 + threadIdx.x;
    int k  = blockIdx.x*32 + threadIdx.y;
    g_wT[k*CH + oc] = tile[threadIdx.x][threadIdx.y];
}

// ---------------- 3x3 conv + bias + relu, writes NHWC ----------------
// MIMICRY of XLA-CPU EigenConv2DF32 (aarch64, ColMajor wrap): per-output
// chain = C += chunk_n, chunk = serial FMA over 248 consecutive k in global
// order k = kx*6144 + ky*2048 + c  (c innermost, ky middle, kx OUTERMOST —
// ColMajor patch dims (C, ky, kx)). 18432 = 74*248 + 80 (remainder last).
// grid (50 rows, 4 oc-tiles, 4 batch), block 256 (16 tx x 16 ty)
__global__ __launch_bounds__(256) void conv3_kernel(const float* __restrict__ feat,
                                                    const float* __restrict__ bias) {
    __shared__ __align__(16) float sw[16*128];   // [c16][oc128]  8KB
    __shared__ __align__(16) float si[16*56];    // [c16][col56]  3.5KB
    int tid = threadIdx.x;
    int tx = tid & 15, ty = tid >> 4;
    int y = blockIdx.x, ocb = blockIdx.y, b = blockIdx.z;

    float acc[8][4];   // current kc-chunk accumulator
    float mst[8][4];   // master C (chunk sums added serially; C=0 start)
#pragma unroll
    for (int o = 0; o < 8; o++)
#pragma unroll
        for (int p = 0; p < 4; p++) { acc[o][p] = 0.f; mst[o][p] = 0.f; }

    int sbase = (tx < 13) ? tx*4 : 0;   // clamp OOB threads to valid smem (results discarded)
    const float* fb = feat + (size_t)b*C_IN*2500;

    int kpos = 0;   // position within current kc chunk (0..CHUNK_K-1)
    for (int tapi = 0; tapi < 9; tapi++) {
        int kx = tapi / 3, ky = tapi - kx*3;     // kx outermost, ky middle, c inner
        int tap = ky*3 + kx;                     // weight layout index (ky,kx)
        int row = y - 1 + ky;
        bool rowok = (row >= 0 && row < 50);
        for (int cc = 0; cc < C_IN; cc += 16) {
            // weights: tap fixed, 16 c-rows of 128 contiguous oc each
#pragma unroll
            for (int l = tid; l < 16*128; l += 256) {
                int oc = l & 127; int c = l >> 7;
                sw[l] = g_wT[((cc + c)*9 + tap)*CH + ocb*128 + oc];
            }
            // input row (y-1+ky), cols -1..54 with zero padding
#pragma unroll
            for (int l = tid; l < 16*56; l += 256) {
                int c = l / 56, s = l - c*56;
                float v = 0.f;
                int col = s - 1;
                if (rowok && s < 52 && col >= 0 && col < 50)
                    v = fb[(cc + c)*2500 + row*50 + col];
                si[l] = v;
            }
            __syncthreads();
#pragma unroll 4
            for (int c = 0; c < 16; c++) {
                const float* ip = &si[c*56 + sbase];
                float4 i0 = *(const float4*)ip;
                float2 i1 = *(const float2*)(ip + 4);
                float iv[6] = {i0.x, i0.y, i0.z, i0.w, i1.x, i1.y};
                const float* wp = &sw[c*128 + ty*8];
                float4 w0 = *(const float4*)wp;
                float4 w1 = *(const float4*)(wp + 4);
                float wv[8] = {w0.x,w0.y,w0.z,w0.w,w1.x,w1.y,w1.z,w1.w};
#pragma unroll
                for (int o = 0; o < 8; o++)
#pragma unroll
                    for (int p = 0; p < 4; p++)
                        acc[o][p] = __fmaf_rn(wv[o], iv[p + kx], acc[o][p]);
                // Eigen gebp chunk boundary (may fall mid-block: 248 % 16 != 0)
                kpos++;
                if (kpos == CHUNK_K) {
#pragma unroll
                    for (int o = 0; o < 8; o++)
#pragma unroll
                        for (int p = 0; p < 4; p++) {
                            mst[o][p] = __fadd_rn(mst[o][p], acc[o][p]);
                            acc[o][p] = 0.f;
                        }
                    kpos = 0;
                }
            }
            __syncthreads();
        }
    }
    // final remainder chunk (18432 % 248 == 80)
#pragma unroll
    for (int o = 0; o < 8; o++)
#pragma unroll
        for (int p = 0; p < 4; p++)
            mst[o][p] = __fadd_rn(mst[o][p], acc[o][p]);
    // epilogue: bias add then relu, NHWC store
    float bs[8];
#pragma unroll
    for (int o = 0; o < 8; o++) bs[o] = bias[ocb*128 + ty*8 + o];
#pragma unroll
    for (int p = 0; p < 4; p++) {
        int x = tx*4 + p;
        if (x < 50) {
            float* dst = &g_h[((b*50 + y)*50 + x)*CH + ocb*128 + ty*8];
            float4 v0, v1;
            v0.x = fmaxf(__fadd_rn(mst[0][p], bs[0]), 0.f);
            v0.y = fmaxf(__fadd_rn(mst[1][p], bs[1]), 0.f);
            v0.z = fmaxf(__fadd_rn(mst[2][p], bs[2]), 0.f);
            v0.w = fmaxf(__fadd_rn(mst[3][p], bs[3]), 0.f);
            v1.x = fmaxf(__fadd_rn(mst[4][p], bs[4]), 0.f);
            v1.y = fmaxf(__fadd_rn(mst[5][p], bs[5]), 0.f);
            v1.z = fmaxf(__fadd_rn(mst[6][p], bs[6]), 0.f);
            v1.w = fmaxf(__fadd_rn(mst[7][p], bs[7]), 0.f);
            *(float4*)dst = v0; *(float4*)(dst+4) = v1;
        }
    }
}

// ---------------- heads: Eigen-mimic dot, kc=248 (chunks 248+248+16) ----------------
__global__ __launch_bounds__(256) void heads_kernel(const float* __restrict__ wcls,
                                                    const float* __restrict__ bcls,
                                                    const float* __restrict__ wreg,
                                                    const float* __restrict__ breg,
                                                    const int* __restrict__ imh,
                                                    const int* __restrict__ imw) {
    extern __shared__ float sm[];
    float* sw = sm;                 // [54][513]
    float* sh = sm + 54*513;        // [4][512]
    float* sd = sh + 4*512;         // [4][54]
    int tid = threadIdx.x;
    for (int l = tid; l < 54*512; l += 256) {
        int o = l >> 9, c = l & 511;
        float v = (o < 18) ? wcls[l] : wreg[l - 18*512];
        sw[o*513 + c] = v;
    }
    int pid0 = blockIdx.x*4;
    for (int l = tid; l < 4*512; l += 256) {
        int px = l >> 9;
        sh[l] = g_h[(pid0 + px)*CH + (l & 511)];
    }
    __syncthreads();
    {
        int px = tid >> 6, j = tid & 63;
        if (j < 54) {
            const float* hv = &sh[px*512];
            const float* wv = &sw[j*513];
            float s = 0.f, a = 0.f;
            int kp = 0;
#pragma unroll 8
            for (int c = 0; c < 512; c++) {
                a = __fmaf_rn(hv[c], wv[c], a);
                if (++kp == CHUNK_K) { s = __fadd_rn(s, a); a = 0.f; kp = 0; }
            }
            s = __fadd_rn(s, a);                   // remainder chunk (16)
            s = __fadd_rn(s, (j < 18) ? bcls[j] : breg[j - 18]);
            sd[px*54 + j] = s;
        }
    }
    __syncthreads();
    if (tid < 36) {
        int px = tid / 9, a = tid % 9;
        int pid = pid0 + px;
        int b = pid / 2500, rem = pid % 2500, y = rem / 50, x = rem % 50;
        const float* d = &sd[px*54];
        float l0 = d[a], l1 = d[9 + a];
        float m = fmaxf(l0, l1);
        float e0 = exp_cr(__fsub_rn(l0, m));
        float e1 = exp_cr(__fsub_rn(l1, m));
        float score = __fdiv_rn(e1, __fadd_rn(e0, e1));
        float dx = d[18 + a*4 + 0], dy = d[18 + a*4 + 1];
        float dw = d[18 + a*4 + 2], dh = d[18 + a*4 + 3];
        const float sizesf[3]  = {128.f, 256.f, 512.f};
        const float ratiosf[3] = {0.5f, 1.f, 2.f};
        float sqf = sqrtf(ratiosf[a % 3]);
        float wsf = __fdiv_rn(sizesf[a / 3], sqf);
        float hsf = __fmul_rn(sizesf[a / 3], sqf);
        float acxf = __fmul_rn(__fadd_rn((float)x, 0.5f), 32.f);
        float acyf = __fmul_rn(__fadd_rn((float)y, 0.5f), 32.f);
        float ax1 = __fsub_rn(acxf, __fmul_rn(wsf, 0.5f));
        float ax2 = __fadd_rn(acxf, __fmul_rn(wsf, 0.5f));
        float ay1 = __fsub_rn(acyf, __fmul_rn(hsf, 0.5f));
        float ay2 = __fadd_rn(acyf, __fmul_rn(hsf, 0.5f));
        float aw = __fsub_rn(ax2, ax1);
        float ah = __fsub_rn(ay2, ay1);
        float acx = __fadd_rn(ax1, __fmul_rn(0.5f, aw));
        float acy = __fadd_rn(ay1, __fmul_rn(0.5f, ah));
        float pcx = __fadd_rn(__fmul_rn(dx, aw), acx);
        float pcy = __fadd_rn(__fmul_rn(dy, ah), acy);
        float pw = __fmul_rn(exp_cr(fminf(dw, 4.f)), aw);
        float ph = __fmul_rn(exp_cr(fminf(dh, 4.f)), ah);
        float limw = (float)imw[0], limh = (float)imh[0];
        float bx1 = fminf(fmaxf(__fsub_rn(pcx, __fmul_rn(pw, 0.5f)), 0.f), limw);
        float by1 = fminf(fmaxf(__fsub_rn(pcy, __fmul_rn(ph, 0.5f)), 0.f), limh);
        float bx2 = fminf(fmaxf(__fadd_rn(pcx, __fmul_rn(pw, 0.5f)), 0.f), limw);
        float by2 = fminf(fmaxf(__fadd_rn(pcy, __fmul_rn(ph, 0.5f)), 0.f), limh);
        int n = (y*50 + x)*9 + a;
        g_scores[b*N_ANCH + n] = score;
        *(float4*)&g_boxes[(b*N_ANCH + n)*4] = make_float4(bx1, by1, bx2, by2);
    }
}

// ---------------- top-2000 per batch: radix threshold + bitonic sort ----------------
__device__ __forceinline__ unsigned int fkey(float f) {
    unsigned int u = __float_as_uint(f);
    return (u & 0x80000000u) ? ~u : (u | 0x80000000u);
}

__global__ __launch_bounds__(1024) void topk_kernel() {
    __shared__ unsigned int hist[256];
    __shared__ unsigned int s_prefix;
    __shared__ int s_k, s_cnt;
    __shared__ unsigned long long keys[4096];
    int b = blockIdx.x, tid = threadIdx.x;
    const float* sc = &g_scores[b*N_ANCH];

    unsigned int prefix = 0; int k = K_PRE;
    for (int pass = 0; pass < 4; pass++) {
        int shift = 24 - pass*8;
        if (tid < 256) hist[tid] = 0;
        __syncthreads();
        unsigned int maskhi = (pass == 0) ? 0u : (0xFFFFFFFFu << (shift + 8));
        for (int i = tid; i < N_ANCH; i += 1024) {
            unsigned int u = fkey(sc[i]);
            if ((u & maskhi) == prefix) atomicAdd(&hist[(u >> shift) & 255], 1u);
        }
        __syncthreads();
        if (tid == 0) {
            int cum = 0;
            for (int d = 255; d >= 0; d--) {
                int c = (int)hist[d];
                if (cum + c >= k) { s_prefix = prefix | ((unsigned)d << shift); s_k = k - cum; break; }
                cum += c;
            }
        }
        __syncthreads();
        prefix = s_prefix; k = s_k;
        __syncthreads();
    }
    if (tid == 0) s_cnt = 0;
    __syncthreads();
    for (int i = tid; i < N_ANCH; i += 1024) {
        unsigned int u = fkey(sc[i]);
        if (u >= prefix) {
            int p = atomicAdd(&s_cnt, 1);
            if (p < 4096)
                keys[p] = ((unsigned long long)u << 32) | (unsigned int)(0xFFFFFFFFu - i);
        }
    }
    __syncthreads();
    int cnt = min(s_cnt, 4096);
    for (int i = tid; i < 4096; i += 1024) if (i >= cnt) keys[i] = 0ULL;
    __syncthreads();
    for (int k2 = 2; k2 <= 4096; k2 <<= 1) {
        for (int s = k2 >> 1; s > 0; s >>= 1) {
            for (int i = tid; i < 4096; i += 1024) {
                int j = i ^ s;
                if (j > i) {
                    bool asc = ((i & k2) != 0);
                    unsigned long long a = keys[i], c = keys[j];
                    if ((a > c) == asc) { keys[i] = c; keys[j] = a; }
                }
            }
            __syncthreads();
        }
    }
    for (int r = tid; r < K_PRE; r += 1024) {
        int idx = (int)(0xFFFFFFFFu - (unsigned int)(keys[r] & 0xFFFFFFFFULL));
        float4 bx = *(const float4*)&g_boxes[(b*N_ANCH + idx)*4];
        *(float4*)&g_btop[(b*K_PRE + r)*4] = bx;
    }
}

// ---------------- IoU bitmask: 2000x2000, 64-bit blocks ----------------
__global__ __launch_bounds__(64) void mask_kernel() {
    __shared__ float4 cb[64];
    int b = blockIdx.z;
    int rb = blockIdx.y*64, cblk = blockIdx.x;
    int t = threadIdx.x;
    int j0 = cblk*64;
    int jn = min(64, K_PRE - j0);
    if (t < jn) cb[t] = *(const float4*)&g_btop[(b*K_PRE + j0 + t)*4];
    __syncthreads();
    int i = rb + t;
    if (i < K_PRE) {
        float4 a = *(const float4*)&g_btop[(b*K_PRE + i)*4];
        float areaA = __fmul_rn(__fsub_rn(a.z, a.x), __fsub_rn(a.w, a.y));
        unsigned long long bits = 0ULL;
        for (int jj = 0; jj < jn; jj++) {
            float4 c = cb[jj];
            float xx1 = fmaxf(a.x, c.x), yy1 = fmaxf(a.y, c.y);
            float xx2 = fminf(a.z, c.z), yy2 = fminf(a.w, c.w);
            float w = fmaxf(__fsub_rn(xx2, xx1), 0.f);
            float h = fmaxf(__fsub_rn(yy2, yy1), 0.f);
            float inter = __fmul_rn(w, h);
            float areaB = __fmul_rn(__fsub_rn(c.z, c.x), __fsub_rn(c.w, c.y));
            float uni = __fadd_rn(__fsub_rn(__fadd_rn(areaA, areaB), inter), 1e-9f);
            float iou = __fdiv_rn(inter, uni);
            if (iou > 0.7f) bits |= (1ULL << jj);
        }
        g_mask[(b*K_PRE + i)*32 + cblk] = bits;
    }
}

// ---------------- serial NMS scan + stable-partition gather ----------------
__global__ __launch_bounds__(256) void nms_scan_kernel(float* __restrict__ out) {
    __shared__ unsigned long long removed[32];
    __shared__ unsigned long long buf[2][64*32];
    __shared__ unsigned char keep[2048];
    __shared__ int ps[256];
    __shared__ int s_tot;
    int b = blockIdx.x, tid = threadIdx.x;

    if (tid < 32) removed[tid] = 0ULL;
    for (int i = tid; i < 2048; i += 256) keep[i] = 0;
    for (int l = tid; l < 2048; l += 256) {
        int r = l >> 5, lane = l & 31;
        buf[0][l] = (r < K_PRE) ? g_mask[(b*K_PRE + r)*32 + lane] : 0ULL;
    }
    __syncthreads();

    for (int ch = 0; ch < 32; ch++) {
        int cur = ch & 1;
        if (tid >= 32) {
            if (ch + 1 < 32) {
                for (int l = tid - 32; l < 2048; l += 224) {
                    int r = l >> 5, lane = l & 31;
                    int i = (ch + 1)*64 + r;
                    buf[cur ^ 1][l] = (i < K_PRE) ? g_mask[(b*K_PRE + i)*32 + lane] : 0ULL;
                }
            }
        } else {
            int lane = tid;
            for (int r = 0; r < 64; r++) {
                int i = ch*64 + r;
                if (i >= K_PRE) break;
                unsigned long long w = removed[i >> 6];
                bool kept = ((w >> (i & 63)) & 1ULL) == 0ULL;
                if (kept) {
                    removed[lane] |= buf[cur][r*32 + lane];
                    if (lane == 0) keep[i] = 1;
                }
                __syncwarp();
            }
        }
        __syncthreads();
    }

    int base = tid*8;
    int c0 = 0;
    for (int e = 0; e < 8; e++) { int idx = base + e; if (idx < K_PRE && keep[idx]) c0++; }
    ps[tid] = c0;
    __syncthreads();
    if (tid == 0) {
        int run = 0;
        for (int t2 = 0; t2 < 256; t2++) { int v = ps[t2]; ps[t2] = run; run += v; }
        s_tot = run;
    }
    __syncthreads();
    int K = s_tot;
    int kb = ps[tid];
    for (int e = 0; e < 8; e++) {
        int idx = base + e;
        if (idx >= K_PRE) break;
        int pos;
        if (keep[idx]) { pos = kb; kb++; }
        else           { pos = K + (idx - kb); }
        if (pos < TOPN) {
            float4 bx = *(const float4*)&g_btop[(b*K_PRE + idx)*4];
            *(float4*)&out[(b*TOPN + pos)*4] = bx;
        }
    }
}

// ---------------- launch ----------------
extern "C" void kernel_launch(void* const* d_in, const int* in_sizes, int n_in,
                              void* d_out, int out_size) {
    (void)in_sizes; (void)n_in; (void)out_size;
    const float* feat   = (const float*)d_in[0];
    const float* w_conv = (const float*)d_in[1];
    const float* b_conv = (const float*)d_in[2];
    const float* w_cls  = (const float*)d_in[3];
    const float* b_cls  = (const float*)d_in[4];
    const float* w_reg  = (const float*)d_in[5];
    const float* b_reg  = (const float*)d_in[6];
    const int*   img_h  = (const int*)d_in[7];
    const int*   img_w  = (const int*)d_in[8];
    float* out = (float*)d_out;

    const int heads_smem = (54*513 + 4*512 + 4*54) * (int)sizeof(float);
    cudaFuncSetAttribute(heads_kernel, cudaFuncAttributeMaxDynamicSharedMemorySize, heads_smem);

    transpose_w_kernel<<<dim3(576, 16), dim3(32, 32)>>>(w_conv);
    conv3_kernel<<<dim3(50, 4, 4), 256>>>(feat, b_conv);
    heads_kernel<<<2500, 256, heads_smem>>>(w_cls, b_cls, w_reg, b_reg, img_h, img_w);
    topk_kernel<<<4, 1024>>>();
    mask_kernel<<<dim3(32, 32, 4), 64>>>();
    nms_scan_kernel<<<4, 256>>>(out);
}

// round 11
// speedup vs baseline: 2.0372x; 2.0372x over previous
#include <cuda_runtime.h>
#include <cstdint>
#include <math.h>

// ---------------- problem constants ----------------
#define BATCH   4
#define C_IN    2048
#define CH      512
#define HWDIM   50
#define A_NUM   9
#define N_ANCH  (HWDIM*HWDIM*A_NUM)   // 22500
#define K_PRE   2000
#define TOPN    1000
#define NPIX    (BATCH*HWDIM*HWDIM)   // 10000
#define KDIM    (C_IN*9)              // 18432

// Eigen gebp kc on aarch64 (default l1=16KB, NEON mr=12/nr=4): kc = 248
#define CHUNK_K 248

// ---------------- device scratch (no allocs allowed) ----------------
__device__ float g_wT2[9*C_IN*CH];                 // [tap][c][oc]        37.7MB
__device__ float g_pad[BATCH*52*C_IN*64];          // padded NCHW->[b][row][c][64] 109MB
__device__ float g_h[NPIX*CH];                     // NHWC conv out  20.5MB
__device__ float g_scores[BATCH*N_ANCH];
__device__ float g_boxes[BATCH*N_ANCH*4];
__device__ float g_btop[BATCH*K_PRE*4];
__device__ unsigned long long g_mask[BATCH*K_PRE*32];

// correctly-rounded float exp: fp64 exp, single rounding to fp32
__device__ __forceinline__ float exp_cr(float x) {
    return (float)exp((double)x);
}

// ---------------- packed f32x2 helpers (bit-exact: 2 independent IEEE FMAs) --
#define FMA2(d, a, b) asm("fma.rn.f32x2 %0, %1, %2, %0;" : "+l"(d) : "l"(a), "l"(b))
#define ADD2(m, a)    asm("add.rn.f32x2 %0, %1, %0;"     : "+l"(m) : "l"(a))
#define SPLAT2(d, v)  asm("mov.b64 %0, {%1, %1};"        : "=l"(d) : "r"(__float_as_uint(v)))

__device__ __forceinline__ void cp16(void* sdst, const void* gsrc) {
    unsigned s = (unsigned)__cvta_generic_to_shared(sdst);
    asm volatile("cp.async.cg.shared.global [%0], [%1], 16;" :: "r"(s), "l"(gsrc));
}
#define CP_COMMIT() asm volatile("cp.async.commit_group;")
#define CP_WAIT1()  asm volatile("cp.async.wait_group 1;")
#define CP_WAIT0()  asm volatile("cp.async.wait_group 0;")

// ---------------- weight prep: [oc][c*9+tap] -> [tap][c][oc] ----------------
__global__ __launch_bounds__(1024) void transpose_w_kernel(const float* __restrict__ w) {
    __shared__ float tile[32][33];
    int kxi = blockIdx.x*32 + threadIdx.x;  // k dim (18432 = 576*32 exact)
    int oy  = blockIdx.y*32 + threadIdx.y;  // oc dim (512 = 16*32 exact)
    tile[threadIdx.y][threadIdx.x] = w[oy*KDIM + kxi];
    __syncthreads();
    int oc = blockIdx.y*32 + threadIdx.x;
    int k  = blockIdx.x*32 + threadIdx.y;
    int c = k / 9, tap = k - c*9;
    g_wT2[(tap*C_IN + c)*CH + oc] = tile[threadIdx.x][threadIdx.y];
}

// ---------------- input prep: zero-padded, [b][row 52][c][64] ----------------
// row r corresponds to input row r-1; col j corresponds to input col j-1.
__global__ __launch_bounds__(256) void pad_kernel(const float* __restrict__ feat) {
    int r = blockIdx.x, cb = blockIdx.y, b = blockIdx.z;
    int tid = threadIdx.x;
    bool rok = (r >= 1 && r <= 50);
    for (int l = tid; l < 128*64; l += 256) {
        int cl = l >> 6, j = l & 63;
        int c = cb*128 + cl;
        float v = 0.f;
        if (rok && j >= 1 && j <= 50)
            v = feat[(b*C_IN + c)*2500 + (r-1)*50 + (j-1)];
        g_pad[((b*52 + r)*C_IN + c)*64 + j] = v;
    }
}

// ---------------- 3x3 conv + bias + relu, writes NHWC ----------------
// Bit-exact Eigen-gebp chain per output (kx outer, ky, c inner; kc=248),
// computed with f32x2 packed FMAs over oc pairs (independent lanes) and a
// cp.async double-buffered pipeline. grid (50, 4, 4), block 256 (16tx x 16ty).
template<int KX>
__device__ __forceinline__ void compute_chunk(
    const float* __restrict__ swb, const float* __restrict__ sib,
    int ty8, int sbase,
    unsigned long long acc[4][4], unsigned long long mst[4][4], int& kpos)
{
#pragma unroll
    for (int c = 0; c < 16; c++) {
        const float* wrow = swb + c*128 + ty8;
        ulonglong2 wA = *(const ulonglong2*)(wrow);
        ulonglong2 wB = *(const ulonglong2*)(wrow + 4);
        unsigned long long wv0 = wA.x, wv1 = wA.y, wv2 = wB.x, wv3 = wB.y;
        const float* irow = sib + c*64 + sbase + KX;
        float v0 = irow[0], v1 = irow[1], v2 = irow[2], v3 = irow[3];
        unsigned long long p0, p1, p2, p3;
        SPLAT2(p0, v0); SPLAT2(p1, v1); SPLAT2(p2, v2); SPLAT2(p3, v3);
        FMA2(acc[0][0], wv0, p0); FMA2(acc[0][1], wv0, p1);
        FMA2(acc[0][2], wv0, p2); FMA2(acc[0][3], wv0, p3);
        FMA2(acc[1][0], wv1, p0); FMA2(acc[1][1], wv1, p1);
        FMA2(acc[1][2], wv1, p2); FMA2(acc[1][3], wv1, p3);
        FMA2(acc[2][0], wv2, p0); FMA2(acc[2][1], wv2, p1);
        FMA2(acc[2][2], wv2, p2); FMA2(acc[2][3], wv2, p3);
        FMA2(acc[3][0], wv3, p0); FMA2(acc[3][1], wv3, p1);
        FMA2(acc[3][2], wv3, p2); FMA2(acc[3][3], wv3, p3);
        if (++kpos == CHUNK_K) {
#pragma unroll
            for (int o = 0; o < 4; o++)
#pragma unroll
                for (int p = 0; p < 4; p++) {
                    ADD2(mst[o][p], acc[o][p]);
                    acc[o][p] = 0ULL;
                }
            kpos = 0;
        }
    }
}

__global__ __launch_bounds__(256, 2) void conv3_kernel(const float* __restrict__ bias) {
    __shared__ __align__(16) float sw[2][16*128];   // 16KB
    __shared__ __align__(16) float si[2][16*64];    //  8KB
    int tid = threadIdx.x;
    int tx = tid & 15, ty = tid >> 4;
    int y = blockIdx.x, ocb = blockIdx.y, b = blockIdx.z;
    int ty8 = ty*8;
    int sbase = (tx < 13) ? tx*4 : 0;   // OOB threads clamped (results discarded)

    unsigned long long acc[4][4], mst[4][4];
#pragma unroll
    for (int o = 0; o < 4; o++)
#pragma unroll
        for (int p = 0; p < 4; p++) { acc[o][p] = 0ULL; mst[o][p] = 0ULL; }

    // ---- chunk loader (3 cp.async per thread) ----
    auto load_chunk = [&](int q, int buf) {
        int tapi = q >> 7;
        int ccq = (q & 127) << 4;
        int kx = tapi / 3, ky = tapi - kx*3;   // kx outermost (Eigen ColMajor patch)
        int tap = ky*3 + kx;                   // weight layout index (ky,kx)
        int row = y + ky;                      // padded row = (y-1+ky)+1
        const float* wsrc = g_wT2 + (tap*C_IN + ccq)*CH + ocb*128;
#pragma unroll
        for (int i = 0; i < 2; i++) {
            int s = tid + 256*i;               // 0..511
            int c = s >> 5, f = (s & 31) * 4;
            cp16(&sw[buf][c*128 + f], wsrc + c*CH + f);
        }
        {
            int c = tid >> 4, f = (tid & 15) * 4;
            const float* isrc = g_pad + ((b*52 + row)*C_IN + ccq + c)*64 + f;
            cp16(&si[buf][c*64 + f], isrc);
        }
    };

    load_chunk(0, 0);
    CP_COMMIT();
    int kpos = 0;
    for (int q = 0; q < 1152; q++) {
        int buf = q & 1;
        if (q + 1 < 1152) {
            load_chunk(q + 1, buf ^ 1);
            CP_COMMIT();
            CP_WAIT1();
        } else {
            CP_WAIT0();
        }
        __syncthreads();
        int tapi = q >> 7;
        int kx = tapi / 3;
        const float* swb = &sw[buf][0];
        const float* sib = &si[buf][0];
        if (kx == 0)      compute_chunk<0>(swb, sib, ty8, sbase, acc, mst, kpos);
        else if (kx == 1) compute_chunk<1>(swb, sib, ty8, sbase, acc, mst, kpos);
        else              compute_chunk<2>(swb, sib, ty8, sbase, acc, mst, kpos);
        __syncthreads();
    }
    // final remainder chunk (18432 % 248 == 80)
#pragma unroll
    for (int o = 0; o < 4; o++)
#pragma unroll
        for (int p = 0; p < 4; p++)
            ADD2(mst[o][p], acc[o][p]);

    // epilogue: bias add then relu, NHWC store
    float bs[8];
#pragma unroll
    for (int o = 0; o < 8; o++) bs[o] = bias[ocb*128 + ty8 + o];
#pragma unroll
    for (int p = 0; p < 4; p++) {
        int x = tx*4 + p;
        if (x < 50) {
            float r[8];
#pragma unroll
            for (int o = 0; o < 4; o++) {
                unsigned long long v = mst[o][p];
                r[2*o]   = __uint_as_float((unsigned)(v & 0xffffffffULL));
                r[2*o+1] = __uint_as_float((unsigned)(v >> 32));
            }
            float* dst = &g_h[((b*50 + y)*50 + x)*CH + ocb*128 + ty8];
            float4 v0, v1;
            v0.x = fmaxf(__fadd_rn(r[0], bs[0]), 0.f);
            v0.y = fmaxf(__fadd_rn(r[1], bs[1]), 0.f);
            v0.z = fmaxf(__fadd_rn(r[2], bs[2]), 0.f);
            v0.w = fmaxf(__fadd_rn(r[3], bs[3]), 0.f);
            v1.x = fmaxf(__fadd_rn(r[4], bs[4]), 0.f);
            v1.y = fmaxf(__fadd_rn(r[5], bs[5]), 0.f);
            v1.z = fmaxf(__fadd_rn(r[6], bs[6]), 0.f);
            v1.w = fmaxf(__fadd_rn(r[7], bs[7]), 0.f);
            *(float4*)dst = v0; *(float4*)(dst+4) = v1;
        }
    }
}

// ---------------- heads: Eigen-mimic dot, kc=248 (chunks 248+248+16) ----------------
__global__ __launch_bounds__(256) void heads_kernel(const float* __restrict__ wcls,
                                                    const float* __restrict__ bcls,
                                                    const float* __restrict__ wreg,
                                                    const float* __restrict__ breg,
                                                    const int* __restrict__ imh,
                                                    const int* __restrict__ imw) {
    extern __shared__ float sm[];
    float* sw = sm;                 // [54][513]
    float* sh = sm + 54*513;        // [4][512]
    float* sd = sh + 4*512;         // [4][54]
    int tid = threadIdx.x;
    for (int l = tid; l < 54*512; l += 256) {
        int o = l >> 9, c = l & 511;
        float v = (o < 18) ? wcls[l] : wreg[l - 18*512];
        sw[o*513 + c] = v;
    }
    int pid0 = blockIdx.x*4;
    for (int l = tid; l < 4*512; l += 256) {
        int px = l >> 9;
        sh[l] = g_h[(pid0 + px)*CH + (l & 511)];
    }
    __syncthreads();
    {
        int px = tid >> 6, j = tid & 63;
        if (j < 54) {
            const float* hv = &sh[px*512];
            const float* wv = &sw[j*513];
            float s = 0.f, a = 0.f;
            int kp = 0;
#pragma unroll 8
            for (int c = 0; c < 512; c++) {
                a = __fmaf_rn(hv[c], wv[c], a);
                if (++kp == CHUNK_K) { s = __fadd_rn(s, a); a = 0.f; kp = 0; }
            }
            s = __fadd_rn(s, a);                   // remainder chunk (16)
            s = __fadd_rn(s, (j < 18) ? bcls[j] : breg[j - 18]);
            sd[px*54 + j] = s;
        }
    }
    __syncthreads();
    if (tid < 36) {
        int px = tid / 9, a = tid % 9;
        int pid = pid0 + px;
        int b = pid / 2500, rem = pid % 2500, y = rem / 50, x = rem % 50;
        const float* d = &sd[px*54];
        float l0 = d[a], l1 = d[9 + a];
        float m = fmaxf(l0, l1);
        float e0 = exp_cr(__fsub_rn(l0, m));
        float e1 = exp_cr(__fsub_rn(l1, m));
        float score = __fdiv_rn(e1, __fadd_rn(e0, e1));
        float dx = d[18 + a*4 + 0], dy = d[18 + a*4 + 1];
        float dw = d[18 + a*4 + 2], dh = d[18 + a*4 + 3];
        const float sizesf[3]  = {128.f, 256.f, 512.f};
        const float ratiosf[3] = {0.5f, 1.f, 2.f};
        float sqf = sqrtf(ratiosf[a % 3]);
        float wsf = __fdiv_rn(sizesf[a / 3], sqf);
        float hsf = __fmul_rn(sizesf[a / 3], sqf);
        float acxf = __fmul_rn(__fadd_rn((float)x, 0.5f), 32.f);
        float acyf = __fmul_rn(__fadd_rn((float)y, 0.5f), 32.f);
        float ax1 = __fsub_rn(acxf, __fmul_rn(wsf, 0.5f));
        float ax2 = __fadd_rn(acxf, __fmul_rn(wsf, 0.5f));
        float ay1 = __fsub_rn(acyf, __fmul_rn(hsf, 0.5f));
        float ay2 = __fadd_rn(acyf, __fmul_rn(hsf, 0.5f));
        float aw = __fsub_rn(ax2, ax1);
        float ah = __fsub_rn(ay2, ay1);
        float acx = __fadd_rn(ax1, __fmul_rn(0.5f, aw));
        float acy = __fadd_rn(ay1, __fmul_rn(0.5f, ah));
        float pcx = __fadd_rn(__fmul_rn(dx, aw), acx);
        float pcy = __fadd_rn(__fmul_rn(dy, ah), acy);
        float pw = __fmul_rn(exp_cr(fminf(dw, 4.f)), aw);
        float ph = __fmul_rn(exp_cr(fminf(dh, 4.f)), ah);
        float limw = (float)imw[0], limh = (float)imh[0];
        float bx1 = fminf(fmaxf(__fsub_rn(pcx, __fmul_rn(pw, 0.5f)), 0.f), limw);
        float by1 = fminf(fmaxf(__fsub_rn(pcy, __fmul_rn(ph, 0.5f)), 0.f), limh);
        float bx2 = fminf(fmaxf(__fadd_rn(pcx, __fmul_rn(pw, 0.5f)), 0.f), limw);
        float by2 = fminf(fmaxf(__fadd_rn(pcy, __fmul_rn(ph, 0.5f)), 0.f), limh);
        int n = (y*50 + x)*9 + a;
        g_scores[b*N_ANCH + n] = score;
        *(float4*)&g_boxes[(b*N_ANCH + n)*4] = make_float4(bx1, by1, bx2, by2);
    }
}

// ---------------- top-2000 per batch: radix threshold + bitonic sort ----------------
__device__ __forceinline__ unsigned int fkey(float f) {
    unsigned int u = __float_as_uint(f);
    return (u & 0x80000000u) ? ~u : (u | 0x80000000u);
}

__global__ __launch_bounds__(1024) void topk_kernel() {
    __shared__ unsigned int hist[256];
    __shared__ unsigned int s_prefix;
    __shared__ int s_k, s_cnt;
    __shared__ unsigned long long keys[4096];
    int b = blockIdx.x, tid = threadIdx.x;
    const float* sc = &g_scores[b*N_ANCH];

    unsigned int prefix = 0; int k = K_PRE;
    for (int pass = 0; pass < 4; pass++) {
        int shift = 24 - pass*8;
        if (tid < 256) hist[tid] = 0;
        __syncthreads();
        unsigned int maskhi = (pass == 0) ? 0u : (0xFFFFFFFFu << (shift + 8));
        for (int i = tid; i < N_ANCH; i += 1024) {
            unsigned int u = fkey(sc[i]);
            if ((u & maskhi) == prefix) atomicAdd(&hist[(u >> shift) & 255], 1u);
        }
        __syncthreads();
        if (tid == 0) {
            int cum = 0;
            for (int d = 255; d >= 0; d--) {
                int c = (int)hist[d];
                if (cum + c >= k) { s_prefix = prefix | ((unsigned)d << shift); s_k = k - cum; break; }
                cum += c;
            }
        }
        __syncthreads();
        prefix = s_prefix; k = s_k;
        __syncthreads();
    }
    if (tid == 0) s_cnt = 0;
    __syncthreads();
    for (int i = tid; i < N_ANCH; i += 1024) {
        unsigned int u = fkey(sc[i]);
        if (u >= prefix) {
            int p = atomicAdd(&s_cnt, 1);
            if (p < 4096)
                keys[p] = ((unsigned long long)u << 32) | (unsigned int)(0xFFFFFFFFu - i);
        }
    }
    __syncthreads();
    int cnt = min(s_cnt, 4096);
    for (int i = tid; i < 4096; i += 1024) if (i >= cnt) keys[i] = 0ULL;
    __syncthreads();
    for (int k2 = 2; k2 <= 4096; k2 <<= 1) {
        for (int s = k2 >> 1; s > 0; s >>= 1) {
            for (int i = tid; i < 4096; i += 1024) {
                int j = i ^ s;
                if (j > i) {
                    bool asc = ((i & k2) != 0);
                    unsigned long long a = keys[i], c = keys[j];
                    if ((a > c) == asc) { keys[i] = c; keys[j] = a; }
                }
            }
            __syncthreads();
        }
    }
    for (int r = tid; r < K_PRE; r += 1024) {
        int idx = (int)(0xFFFFFFFFu - (unsigned int)(keys[r] & 0xFFFFFFFFULL));
        float4 bx = *(const float4*)&g_boxes[(b*N_ANCH + idx)*4];
        *(float4*)&g_btop[(b*K_PRE + r)*4] = bx;
    }
}

// ---------------- IoU bitmask: 2000x2000, 64-bit blocks ----------------
__global__ __launch_bounds__(64) void mask_kernel() {
    __shared__ float4 cb[64];
    int b = blockIdx.z;
    int rb = blockIdx.y*64, cblk = blockIdx.x;
    int t = threadIdx.x;
    int j0 = cblk*64;
    int jn = min(64, K_PRE - j0);
    if (t < jn) cb[t] = *(const float4*)&g_btop[(b*K_PRE + j0 + t)*4];
    __syncthreads();
    int i = rb + t;
    if (i < K_PRE) {
        float4 a = *(const float4*)&g_btop[(b*K_PRE + i)*4];
        float areaA = __fmul_rn(__fsub_rn(a.z, a.x), __fsub_rn(a.w, a.y));
        unsigned long long bits = 0ULL;
        for (int jj = 0; jj < jn; jj++) {
            float4 c = cb[jj];
            float xx1 = fmaxf(a.x, c.x), yy1 = fmaxf(a.y, c.y);
            float xx2 = fminf(a.z, c.z), yy2 = fminf(a.w, c.w);
            float w = fmaxf(__fsub_rn(xx2, xx1), 0.f);
            float h = fmaxf(__fsub_rn(yy2, yy1), 0.f);
            float inter = __fmul_rn(w, h);
            float areaB = __fmul_rn(__fsub_rn(c.z, c.x), __fsub_rn(c.w, c.y));
            float uni = __fadd_rn(__fsub_rn(__fadd_rn(areaA, areaB), inter), 1e-9f);
            float iou = __fdiv_rn(inter, uni);
            if (iou > 0.7f) bits |= (1ULL << jj);
        }
        g_mask[(b*K_PRE + i)*32 + cblk] = bits;
    }
}

// ---------------- serial NMS scan + stable-partition gather ----------------
__global__ __launch_bounds__(256) void nms_scan_kernel(float* __restrict__ out) {
    __shared__ unsigned long long removed[32];
    __shared__ unsigned long long buf[2][64*32];
    __shared__ unsigned char keep[2048];
    __shared__ int ps[256];
    __shared__ int s_tot;
    int b = blockIdx.x, tid = threadIdx.x;

    if (tid < 32) removed[tid] = 0ULL;
    for (int i = tid; i < 2048; i += 256) keep[i] = 0;
    for (int l = tid; l < 2048; l += 256) {
        int r = l >> 5, lane = l & 31;
        buf[0][l] = (r < K_PRE) ? g_mask[(b*K_PRE + r)*32 + lane] : 0ULL;
    }
    __syncthreads();

    for (int ch = 0; ch < 32; ch++) {
        int cur = ch & 1;
        if (tid >= 32) {
            if (ch + 1 < 32) {
                for (int l = tid - 32; l < 2048; l += 224) {
                    int r = l >> 5, lane = l & 31;
                    int i = (ch + 1)*64 + r;
                    buf[cur ^ 1][l] = (i < K_PRE) ? g_mask[(b*K_PRE + i)*32 + lane] : 0ULL;
                }
            }
        } else {
            int lane = tid;
            for (int r = 0; r < 64; r++) {
                int i = ch*64 + r;
                if (i >= K_PRE) break;
                unsigned long long w = removed[i >> 6];
                bool kept = ((w >> (i & 63)) & 1ULL) == 0ULL;
                if (kept) {
                    removed[lane] |= buf[cur][r*32 + lane];
                    if (lane == 0) keep[i] = 1;
                }
                __syncwarp();
            }
        }
        __syncthreads();
    }

    int base = tid*8;
    int c0 = 0;
    for (int e = 0; e < 8; e++) { int idx = base + e; if (idx < K_PRE && keep[idx]) c0++; }
    ps[tid] = c0;
    __syncthreads();
    if (tid == 0) {
        int run = 0;
        for (int t2 = 0; t2 < 256; t2++) { int v = ps[t2]; ps[t2] = run; run += v; }
        s_tot = run;
    }
    __syncthreads();
    int K = s_tot;
    int kb = ps[tid];
    for (int e = 0; e < 8; e++) {
        int idx = base + e;
        if (idx >= K_PRE) break;
        int pos;
        if (keep[idx]) { pos = kb; kb++; }
        else           { pos = K + (idx - kb); }
        if (pos < TOPN) {
            float4 bx = *(const float4*)&g_btop[(b*K_PRE + idx)*4];
            *(float4*)&out[(b*TOPN + pos)*4] = bx;
        }
    }
}

// ---------------- launch ----------------
extern "C" void kernel_launch(void* const* d_in, const int* in_sizes, int n_in,
                              void* d_out, int out_size) {
    (void)in_sizes; (void)n_in; (void)out_size;
    const float* feat   = (const float*)d_in[0];
    const float* w_conv = (const float*)d_in[1];
    const float* b_conv = (const float*)d_in[2];
    const float* w_cls  = (const float*)d_in[3];
    const float* b_cls  = (const float*)d_in[4];
    const float* w_reg  = (const float*)d_in[5];
    const float* b_reg  = (const float*)d_in[6];
    const int*   img_h  = (const int*)d_in[7];
    const int*   img_w  = (const int*)d_in[8];
    float* out = (float*)d_out;

    const int heads_smem = (54*513 + 4*512 + 4*54) * (int)sizeof(float);
    cudaFuncSetAttribute(heads_kernel, cudaFuncAttributeMaxDynamicSharedMemorySize, heads_smem);

    transpose_w_kernel<<<dim3(576, 16), dim3(32, 32)>>>(w_conv);
    pad_kernel<<<dim3(52, 16, 4), 256>>>(feat);
    conv3_kernel<<<dim3(50, 4, 4), 256>>>(b_conv);
    heads_kernel<<<2500, 256, heads_smem>>>(w_cls, b_cls, w_reg, b_reg, img_h, img_w);
    topk_kernel<<<4, 1024>>>();
    mask_kernel<<<dim3(32, 32, 4), 64>>>();
    nms_scan_kernel<<<4, 256>>>(out);
}